// round 14
// baseline (speedup 1.0000x reference)
#include <cuda_runtime.h>
#include <cuda_fp16.h>
#include <cstdint>
#include <cstddef>

#define BB  8192
#define TT  8
#define PPD 256
#define GGD 512
#define CCH 768
#define H0  512
#define H1  256

// ------------------------- device scratch (352 MB total) -------------------
__device__ __align__(256) __half g_comb_h [(size_t)BB*CCH];
__device__ __align__(256) __half g_comb_l [(size_t)BB*CCH];
__device__ __align__(256) __half g_pers_h [(size_t)BB*GGD];
__device__ __align__(256) __half g_pers_l [(size_t)BB*GGD];
__device__ __align__(256) __half g_wppn0_h[(size_t)TT*H0*CCH];
__device__ __align__(256) __half g_wppn0_l[(size_t)TT*H0*CCH];
__device__ __align__(256) __half g_wgt0_h [(size_t)TT*H0*H0];
__device__ __align__(256) __half g_wgt0_l [(size_t)TT*H0*H0];
__device__ __align__(256) __half g_wtw0_h [(size_t)TT*H0*GGD];
__device__ __align__(256) __half g_wtw0_l [(size_t)TT*H0*GGD];
__device__ __align__(256) __half g_wppn1_h[(size_t)TT*H1*CCH];
__device__ __align__(256) __half g_wppn1_l[(size_t)TT*H1*CCH];
__device__ __align__(256) __half g_wgt1_h [(size_t)TT*H1*H1];
__device__ __align__(256) __half g_wgt1_l [(size_t)TT*H1*H1];
__device__ __align__(256) __half g_wtw1_h [(size_t)TT*H1*H0];
__device__ __align__(256) __half g_wtw1_l [(size_t)TT*H1*H0];

// Aliased activation pools (stream order makes every overwrite safe; see R5/R6)
#define P64  67108864ull
#define P32  33554432ull
__device__ __align__(256) unsigned char g_poolA[2ull*P64];
__device__ __align__(256) unsigned char g_poolB[2ull*P64];

enum { HP_COMB=0, HP_PERS, HP_WPPN0, HP_WGT0, HP_WTW0, HP_WPPN1, HP_WGT1, HP_WTW1,
       HP_H0, HP_X0, HP_G0, HP_H1, HP_G1, HP_X1 };

__device__ __forceinline__ __half* get_hbuf(int id, int plane){
    switch(id){
        case HP_COMB:  return plane ? g_comb_l  : g_comb_h;
        case HP_PERS:  return plane ? g_pers_l  : g_pers_h;
        case HP_WPPN0: return plane ? g_wppn0_l : g_wppn0_h;
        case HP_WGT0:  return plane ? g_wgt0_l  : g_wgt0_h;
        case HP_WTW0:  return plane ? g_wtw0_l  : g_wtw0_h;
        case HP_WPPN1: return plane ? g_wppn1_l : g_wppn1_h;
        case HP_WGT1:  return plane ? g_wgt1_l  : g_wgt1_h;
        case HP_WTW1:  return plane ? g_wtw1_l  : g_wtw1_h;
        case HP_H0:    return (__half*)(g_poolA + (plane ? P64 : 0));
        case HP_X0:    return (__half*)(g_poolA + (plane ? P64 : 0));
        case HP_G0:    return (__half*)(g_poolB + (plane ? P64 : 0));
        case HP_H1:    return (__half*)(g_poolB + (plane ? P32 : 0));
        case HP_G1:    return (__half*)(g_poolB + P64 + (plane ? P32 : 0));
        default:       return (__half*)(g_poolB + (plane ? P32 : 0));   // HP_X1
    }
}

// ------------------------- small helpers ----------------------------------
__device__ __forceinline__ uint32_t smem_u32(const void* p){
    uint32_t a;
    asm("{ .reg .u64 t; cvta.to.shared.u64 t, %1; cvt.u32.u64 %0, t; }" : "=r"(a) : "l"(p));
    return a;
}
__device__ __forceinline__ void split_f32(float v, __half& hi, __half& lo){
    hi = __float2half_rn(v);
    lo = __float2half_rn(v - __half2float(hi));
}
__device__ __forceinline__ void cp16(uint32_t dst, const void* src){
    asm volatile("cp.async.cg.shared.global [%0], [%1], 16;" :: "r"(dst), "l"(src));
}
#define CP_COMMIT() asm volatile("cp.async.commit_group;" ::: "memory")
// SW128 swizzle: bits [6:4] ^= bits [9:7] — conflict-free ldmatrix at 128B rows
__device__ __forceinline__ uint32_t sw128(uint32_t off){ return off ^ ((off >> 3) & 0x70); }
#define LDSM_X4(r0,r1,r2,r3,addr) \
    asm volatile("ldmatrix.sync.aligned.m8n8.x4.shared.b16 {%0,%1,%2,%3}, [%4];" \
        : "=r"(r0), "=r"(r1), "=r"(r2), "=r"(r3) : "r"(addr))
#define MMA16816(d, a, b0, b1) \
    asm volatile("mma.sync.aligned.m16n8k16.row.col.f32.f16.f16.f32 " \
        "{%0,%1,%2,%3}, {%4,%5,%6,%7}, {%8,%9}, {%0,%1,%2,%3};" \
        : "+f"((d)[0]), "+f"((d)[1]), "+f"((d)[2]), "+f"((d)[3]) \
        : "r"((a)[0]), "r"((a)[1]), "r"((a)[2]), "r"((a)[3]), "r"(b0), "r"(b1))

// ------------------------- prep kernels -----------------------------------
__global__ void concat_convert_k(const float* __restrict__ prior, const float* __restrict__ gen){
    int i = blockIdx.x * blockDim.x + threadIdx.x;
    if (i >= BB * CCH) return;
    int b = i / CCH, c = i % CCH;
    float v = (c < PPD) ? prior[(size_t)b * PPD + c] : gen[(size_t)b * GGD + (c - PPD)];
    __half hi, lo; split_f32(v, hi, lo);
    g_comb_h[i] = hi; g_comb_l[i] = lo;
}
__global__ void pers_convert_k(const float* __restrict__ pers){
    int i = blockIdx.x * blockDim.x + threadIdx.x;
    if (i >= BB * GGD) return;
    __half hi, lo; split_f32(pers[i], hi, lo);
    g_pers_h[i] = hi; g_pers_l[i] = lo;
}

// One fused kernel transposes+converts ALL six weights.
__global__ void transpose_all_k(const float* __restrict__ Wp0, const float* __restrict__ Wg0,
                                const float* __restrict__ Wt0, const float* __restrict__ Wp1,
                                const float* __restrict__ Wg1, const float* __restrict__ Wt1){
    __shared__ float tile[32][33];
    int t = blockIdx.z;
    int bid = blockIdx.x;
    const float* src; __half* dh; __half* dl; int Kd, Nd, idx;
    if      (bid < 384)  { src=Wp0; dh=g_wppn0_h; dl=g_wppn0_l; Kd=CCH; Nd=H0; idx=bid; }
    else if (bid < 640)  { src=Wg0; dh=g_wgt0_h;  dl=g_wgt0_l;  Kd=H0;  Nd=H0; idx=bid-384; }
    else if (bid < 896)  { src=Wt0; dh=g_wtw0_h;  dl=g_wtw0_l;  Kd=GGD; Nd=H0; idx=bid-640; }
    else if (bid < 1088) { src=Wp1; dh=g_wppn1_h; dl=g_wppn1_l; Kd=CCH; Nd=H1; idx=bid-896; }
    else if (bid < 1152) { src=Wg1; dh=g_wgt1_h;  dl=g_wgt1_l;  Kd=H1;  Nd=H1; idx=bid-1088; }
    else                 { src=Wt1; dh=g_wtw1_h;  dl=g_wtw1_l;  Kd=H0;  Nd=H1; idx=bid-1152; }
    int kt = Kd / 32;
    int k0 = (idx % kt) * 32, n0 = (idx / kt) * 32;
    src += (size_t)t * Kd * Nd;
    dh  += (size_t)t * Nd * Kd;
    dl  += (size_t)t * Nd * Kd;
    int x = threadIdx.x;
    for (int yy = threadIdx.y; yy < 32; yy += 8)
        tile[yy][x] = src[(size_t)(k0 + yy) * Nd + n0 + x];
    __syncthreads();
    for (int yy = threadIdx.y; yy < 32; yy += 8){
        float v = tile[x][yy];
        __half hi, lo; split_f32(v, hi, lo);
        size_t o = (size_t)(n0 + yy) * Kd + k0 + x;
        dh[o] = hi; dl[o] = lo;
    }
}

// ------------------------- fp16-split GEMM ---------------------------------
// CTA 128x128, 8 warps (2M x 4N), warp tile 64x32 (LDSM-optimal: 8 LDSM / 32 MMA).
// KC=64, 2-stage, SW128, one __syncthreads per chunk.
// BPL=2: D = Ah*Bh + Ah*Bl (activations rounded; weights near-exact)
// BPL=1: D = Ah*Bh        (gates only; B-round error sigmoid-damped)
// wlo=0 skips the lo-plane output store (x0's lo plane has no consumer).
#define ROWB 128
#define TILEB 16384
#define STG   49152
#define SMEM_DYN (2*STG)

template<int BPL>
__global__ void __launch_bounds__(256, 2) gemm_fp16s(
    int a_id, size_t a_tstr, int lda, int K,
    int b_id, const float* __restrict__ bias,
    int aux_id, int out_id, int Ntot, int epi, int wlo)
{
    extern __shared__ char smem[];
    uint32_t sb = smem_u32(smem);
    int tid = threadIdx.x, wid = tid >> 5, lid = tid & 31;
    int warp_m = wid & 1, warp_n = wid >> 1;     // 2 M-blocks x 4 N-blocks
    int t  = blockIdx.z;
    int m0 = blockIdx.x * 128;
    int n0 = blockIdx.y * 128;

    const __half* Ah = get_hbuf(a_id, 0) + (size_t)t * a_tstr + (size_t)m0 * lda;
    const __half* Bh = get_hbuf(b_id, 0) + ((size_t)t * Ntot + n0) * K;
    const __half* Bl = get_hbuf(b_id, 1) + ((size_t)t * Ntot + n0) * K;

    float acc[4][4][4];
    #pragma unroll
    for (int mi = 0; mi < 4; mi++)
        #pragma unroll
        for (int ni = 0; ni < 4; ni++)
            #pragma unroll
            for (int j = 0; j < 4; j++) acc[mi][ni][j] = 0.f;

    int nk = K >> 6;

    // ---- lane-constant ldmatrix base offsets (s=0); s-step is XOR (s<<5) ----
    // Base bits [6:5] are zero (cb is 0/16), so +s*32 never carries; SW128 mask
    // depends only on row bits [9:7]. (Validated in R13: bitwise-equal result.)
    int lq = lid >> 3, lr = lid & 7;
    uint32_t a_row = (uint32_t)(warp_m * 64 + ((lq & 1) << 3) + lr);
    uint32_t a_cb  = (uint32_t)((lq >> 1) << 4);
    uint32_t b_row = (uint32_t)(warp_n * 32 + ((lq >> 1) << 3) + lr);
    uint32_t b_cb  = (uint32_t)((lq & 1) << 4);
    uint32_t aoff0[4], boff0[2];
    #pragma unroll
    for (int mi = 0; mi < 4; mi++)
        aoff0[mi] = sw128((a_row + mi * 16) * ROWB + a_cb);
    #pragma unroll
    for (int p = 0; p < 2; p++)
        boff0[p] = sw128((b_row + p * 16) * ROWB + b_cb);

    // ---- loader: tiles x 1024 16B-slots; 256 threads x 4 slots per tile ----
    int c8  = tid & 7;
    int r32 = tid >> 3;
    uint32_t dofs[4];
    #pragma unroll
    for (int i = 0; i < 4; i++)
        dofs[i] = sw128((uint32_t)((r32 + 32 * i) * ROWB + c8 * 16));

    auto load_chunk = [&](int kc, int stage_sel){
        uint32_t stg = (uint32_t)stage_sel * (uint32_t)STG;
        const __half* sA = Ah + kc * 64;
        const __half* sH = Bh + kc * 64;
        uint32_t baseA = sb + stg;
        uint32_t baseH = sb + stg + (uint32_t)TILEB;
        #pragma unroll
        for (int i = 0; i < 4; i++){
            int row = r32 + 32 * i;
            cp16(baseA + dofs[i], sA + (size_t)row * lda + c8 * 8);
            cp16(baseH + dofs[i], sH + (size_t)row * K   + c8 * 8);
        }
        if (BPL == 2){
            const __half* sL = Bl + kc * 64;
            uint32_t baseL = sb + stg + 2u * (uint32_t)TILEB;
            #pragma unroll
            for (int i = 0; i < 4; i++){
                int row = r32 + 32 * i;
                cp16(baseL + dofs[i], sL + (size_t)row * K + c8 * 8);
            }
        }
        CP_COMMIT();
    };

    load_chunk(0, 0);

    for (int kc = 0; kc < nk; kc++){
        asm volatile("cp.async.wait_group 0;" ::: "memory");
        __syncthreads();   // loads of kc visible; all warps done reading other stage
        if (kc + 1 < nk)
            load_chunk(kc + 1, (kc + 1) & 1);   // overlaps compute of kc

        uint32_t stg_b = sb + (uint32_t)(kc & 1) * STG;
        uint32_t sAh = stg_b;
        uint32_t sBh = stg_b + TILEB;
        uint32_t sBl = stg_b + 2 * TILEB;

        #pragma unroll
        for (int s = 0; s < 4; s++){
            uint32_t sx = (uint32_t)(s << 5);
            uint32_t ah[4][4];
            #pragma unroll
            for (int mi = 0; mi < 4; mi++)
                LDSM_X4(ah[mi][0], ah[mi][1], ah[mi][2], ah[mi][3], sAh + (aoff0[mi] ^ sx));
            #pragma unroll
            for (int p = 0; p < 2; p++){
                uint32_t bh0, bh1, bh2, bh3;
                uint32_t bl0, bl1, bl2, bl3;
                LDSM_X4(bh0, bh1, bh2, bh3, sBh + (boff0[p] ^ sx));
                if (BPL == 2){
                    LDSM_X4(bl0, bl1, bl2, bl3, sBl + (boff0[p] ^ sx));
                }
                #pragma unroll
                for (int mi = 0; mi < 4; mi++){
                    MMA16816(acc[mi][2*p],   ah[mi], bh0, bh1);
                    MMA16816(acc[mi][2*p+1], ah[mi], bh2, bh3);
                    if (BPL == 2){
                        MMA16816(acc[mi][2*p],   ah[mi], bl0, bl1);
                        MMA16816(acc[mi][2*p+1], ah[mi], bl2, bl3);
                    }
                }
            }
        }
    }

    // ---------------- epilogue ----------------
    const float* biasp = bias + (size_t)t * Ntot;
    const __half* axh = nullptr; const __half* axl = nullptr;
    if (epi){
        axh = get_hbuf(aux_id, 0) + (size_t)t * BB * Ntot;
        axl = get_hbuf(aux_id, 1) + (size_t)t * BB * Ntot;
    }
    __half* oh = get_hbuf(out_id, 0) + (size_t)t * BB * Ntot;
    __half* ol = get_hbuf(out_id, 1) + (size_t)t * BB * Ntot;

    int g = lid >> 2, tig = lid & 3;
    #pragma unroll
    for (int mi = 0; mi < 4; mi++){
        #pragma unroll
        for (int ni = 0; ni < 4; ni++){
            int col = n0 + warp_n * 32 + ni * 8 + 2 * tig;
            float2 bv = *(const float2*)(biasp + col);
            int row0 = m0 + warp_m * 64 + mi * 16 + g;
            #pragma unroll
            for (int h = 0; h < 2; h++){
                int row = row0 + h * 8;
                size_t off = (size_t)row * Ntot + col;
                float v0 = acc[mi][ni][2*h]   + bv.x;
                float v1 = acc[mi][ni][2*h+1] + bv.y;
                float a0 = 0.f, a1 = 0.f;
                if (epi){
                    __half2 hv = *(const __half2*)(axh + off);
                    __half2 lv = *(const __half2*)(axl + off);
                    a0 = __half2float(hv.x) + __half2float(lv.x);
                    a1 = __half2float(hv.y) + __half2float(lv.y);
                }
                float r0, r1;
                if (epi == 0){
                    r0 = fmaxf(v0, 0.f); r1 = fmaxf(v1, 0.f);
                } else if (epi == 1){
                    r0 = a0 * (1.f / (1.f + __expf(-2.f * v0)));
                    r1 = a1 * (1.f / (1.f + __expf(-2.f * v1)));
                } else {
                    r0 = fmaxf(v0 * a0, 0.f); r1 = fmaxf(v1 * a1, 0.f);
                }
                __half h0v, l0v, h1v, l1v;
                split_f32(r0, h0v, l0v); split_f32(r1, h1v, l1v);
                *(__half2*)(oh + off) = __halves2half2(h0v, h1v);
                if (wlo)
                    *(__half2*)(ol + off) = __halves2half2(l0v, l1v);
            }
        }
    }
}

// ------------------------- output layer -----------------------------------
__global__ void out_k(const float* __restrict__ W2, const float* __restrict__ b2,
                      float* __restrict__ out){
    int b = blockIdx.x;
    int wid = threadIdx.x >> 5, lid = threadIdx.x & 31;   // wid = task
    const __half* xh = get_hbuf(HP_X1, 0) + ((size_t)wid * BB + b) * H1;
    const __half* xl = get_hbuf(HP_X1, 1) + ((size_t)wid * BB + b) * H1;
    const float* wr = W2 + (size_t)wid * H1;
    float s = 0.f;
    #pragma unroll
    for (int j = 0; j < 8; j++){
        int i = lid + 32 * j;
        s += (__half2float(xh[i]) + __half2float(xl[i])) * wr[i];
    }
    #pragma unroll
    for (int o = 16; o > 0; o >>= 1)
        s += __shfl_down_sync(0xFFFFFFFFu, s, o);
    if (lid == 0) out[(size_t)b * TT + wid] = s + b2[wid];
}

// ------------------------- launch -----------------------------------------
extern "C" void kernel_launch(void* const* d_in, const int* in_sizes, int n_in,
                              void* d_out, int out_size) {
    const float* prior    = (const float*)d_in[0];
    const float* gen      = (const float*)d_in[1];
    const float* pers     = (const float*)d_in[2];
    const float* tower_W0 = (const float*)d_in[3];
    const float* tower_b0 = (const float*)d_in[4];
    const float* tower_W1 = (const float*)d_in[5];
    const float* tower_b1 = (const float*)d_in[6];
    const float* tower_W2 = (const float*)d_in[7];
    const float* tower_b2 = (const float*)d_in[8];
    const float* ppn0_W   = (const float*)d_in[9];
    const float* ppn0_b   = (const float*)d_in[10];
    const float* gate0_W  = (const float*)d_in[11];
    const float* gate0_b  = (const float*)d_in[12];
    const float* ppn1_W   = (const float*)d_in[13];
    const float* ppn1_b   = (const float*)d_in[14];
    const float* gate1_W  = (const float*)d_in[15];
    const float* gate1_b  = (const float*)d_in[16];

    cudaFuncSetAttribute(gemm_fp16s<2>,
                         cudaFuncAttributeMaxDynamicSharedMemorySize, SMEM_DYN);
    cudaFuncSetAttribute(gemm_fp16s<1>,
                         cudaFuncAttributeMaxDynamicSharedMemorySize, SMEM_DYN);

    // launches 0,1,2: prep — launch index 5 (ncu -s 5 -c 1) is tower0 GEMM
    concat_convert_k<<<(BB * CCH) / 256, 256>>>(prior, gen);
    pers_convert_k<<<(BB * GGD) / 256, 256>>>(pers);
    transpose_all_k<<<dim3(1280, 1, TT), dim3(32, 8)>>>(
        ppn0_W, gate0_W, tower_W0, ppn1_W, gate1_W, tower_W1);

    // ppn0: h0 = relu(comb @ W + b)                 [K=768, N=512]   2-plane
    gemm_fp16s<2><<<dim3(BB/128, H0/128, TT), 256, SMEM_DYN>>>(
        HP_COMB, 0, CCH, CCH, HP_WPPN0, ppn0_b, 0, HP_H0, H0, 0, 1);
    // gate0: g0 = h0 * sigmoid(2*(h0 @ Wg + b))     [K=512, N=512]   1-plane (damped)
    gemm_fp16s<1><<<dim3(BB/128, H0/128, TT), 256, SMEM_DYN>>>(
        HP_H0, (size_t)BB*H0, H0, H0, HP_WGT0, gate0_b, HP_H0, HP_G0, H0, 1, 1);
    // tower0: x0 = relu((pers @ W0 + b0) * g0)      [K=512, N=512]   2-plane (profiled)
    gemm_fp16s<2><<<dim3(BB/128, H0/128, TT), 256, SMEM_DYN>>>(
        HP_PERS, 0, GGD, GGD, HP_WTW0, tower_b0, HP_G0, HP_X0, H0, 2, 0);
    // ppn1: h1 = relu(comb @ W + b)                 [K=768, N=256]   2-plane
    gemm_fp16s<2><<<dim3(BB/128, H1/128, TT), 256, SMEM_DYN>>>(
        HP_COMB, 0, CCH, CCH, HP_WPPN1, ppn1_b, 0, HP_H1, H1, 0, 1);
    // gate1: g1 = h1 * sigmoid(2*(h1 @ Wg + b))     [K=256, N=256]   1-plane (damped)
    gemm_fp16s<1><<<dim3(BB/128, H1/128, TT), 256, SMEM_DYN>>>(
        HP_H1, (size_t)BB*H1, H1, H1, HP_WGT1, gate1_b, HP_H1, HP_G1, H1, 1, 1);
    // tower1: x1 = relu((x0 @ W1 + b1) * g1)        [K=512, N=256]   2-plane
    gemm_fp16s<2><<<dim3(BB/128, H1/128, TT), 256, SMEM_DYN>>>(
        HP_X0, (size_t)BB*H0, H0, H0, HP_WTW1, tower_b1, HP_G1, HP_X1, H1, 2, 1);

    out_k<<<BB, 256>>>(tower_W2, tower_b2, (float*)d_out);
}

// round 16
// speedup vs baseline: 1.0412x; 1.0412x over previous
#include <cuda_runtime.h>
#include <cuda_fp16.h>
#include <cstdint>
#include <cstddef>

#define BB  8192
#define TT  8
#define PPD 256
#define GGD 512
#define CCH 768
#define H0  512
#define H1  256

// ------------------------- device scratch (352 MB total) -------------------
__device__ __align__(256) __half g_comb_h [(size_t)BB*CCH];
__device__ __align__(256) __half g_comb_l [(size_t)BB*CCH];
__device__ __align__(256) __half g_pers_h [(size_t)BB*GGD];
__device__ __align__(256) __half g_pers_l [(size_t)BB*GGD];
__device__ __align__(256) __half g_wppn0_h[(size_t)TT*H0*CCH];
__device__ __align__(256) __half g_wppn0_l[(size_t)TT*H0*CCH];
__device__ __align__(256) __half g_wgt0_h [(size_t)TT*H0*H0];
__device__ __align__(256) __half g_wgt0_l [(size_t)TT*H0*H0];
__device__ __align__(256) __half g_wtw0_h [(size_t)TT*H0*GGD];
__device__ __align__(256) __half g_wtw0_l [(size_t)TT*H0*GGD];
__device__ __align__(256) __half g_wppn1_h[(size_t)TT*H1*CCH];
__device__ __align__(256) __half g_wppn1_l[(size_t)TT*H1*CCH];
__device__ __align__(256) __half g_wgt1_h [(size_t)TT*H1*H1];
__device__ __align__(256) __half g_wgt1_l [(size_t)TT*H1*H1];
__device__ __align__(256) __half g_wtw1_h [(size_t)TT*H1*H0];
__device__ __align__(256) __half g_wtw1_l [(size_t)TT*H1*H0];

// Aliased activation pools (stream order makes every overwrite safe; see R5/R6)
#define P64  67108864ull
#define P32  33554432ull
__device__ __align__(256) unsigned char g_poolA[2ull*P64];
__device__ __align__(256) unsigned char g_poolB[2ull*P64];

enum { HP_COMB=0, HP_PERS, HP_WPPN0, HP_WGT0, HP_WTW0, HP_WPPN1, HP_WGT1, HP_WTW1,
       HP_H0, HP_X0, HP_G0, HP_H1, HP_G1, HP_X1 };

__device__ __forceinline__ __half* get_hbuf(int id, int plane){
    switch(id){
        case HP_COMB:  return plane ? g_comb_l  : g_comb_h;
        case HP_PERS:  return plane ? g_pers_l  : g_pers_h;
        case HP_WPPN0: return plane ? g_wppn0_l : g_wppn0_h;
        case HP_WGT0:  return plane ? g_wgt0_l  : g_wgt0_h;
        case HP_WTW0:  return plane ? g_wtw0_l  : g_wtw0_h;
        case HP_WPPN1: return plane ? g_wppn1_l : g_wppn1_h;
        case HP_WGT1:  return plane ? g_wgt1_l  : g_wgt1_h;
        case HP_WTW1:  return plane ? g_wtw1_l  : g_wtw1_h;
        case HP_H0:    return (__half*)(g_poolA + (plane ? P64 : 0));
        case HP_X0:    return (__half*)(g_poolA + (plane ? P64 : 0));
        case HP_G0:    return (__half*)(g_poolB + (plane ? P64 : 0));
        case HP_H1:    return (__half*)(g_poolB + (plane ? P32 : 0));
        case HP_G1:    return (__half*)(g_poolB + P64 + (plane ? P32 : 0));
        default:       return (__half*)(g_poolB + (plane ? P32 : 0));   // HP_X1
    }
}

// ------------------------- small helpers ----------------------------------
__device__ __forceinline__ uint32_t smem_u32(const void* p){
    uint32_t a;
    asm("{ .reg .u64 t; cvta.to.shared.u64 t, %1; cvt.u32.u64 %0, t; }" : "=r"(a) : "l"(p));
    return a;
}
__device__ __forceinline__ void split_f32(float v, __half& hi, __half& lo){
    hi = __float2half_rn(v);
    lo = __float2half_rn(v - __half2float(hi));
}
__device__ __forceinline__ void cp16(uint32_t dst, const void* src){
    asm volatile("cp.async.cg.shared.global [%0], [%1], 16;" :: "r"(dst), "l"(src));
}
#define CP_COMMIT() asm volatile("cp.async.commit_group;" ::: "memory")
// SW128 swizzle: bits [6:4] ^= bits [9:7] — conflict-free ldmatrix at 128B rows
__device__ __forceinline__ uint32_t sw128(uint32_t off){ return off ^ ((off >> 3) & 0x70); }
#define LDSM_X4(r0,r1,r2,r3,addr) \
    asm volatile("ldmatrix.sync.aligned.m8n8.x4.shared.b16 {%0,%1,%2,%3}, [%4];" \
        : "=r"(r0), "=r"(r1), "=r"(r2), "=r"(r3) : "r"(addr))
#define MMA16816(d, a, b0, b1) \
    asm volatile("mma.sync.aligned.m16n8k16.row.col.f32.f16.f16.f32 " \
        "{%0,%1,%2,%3}, {%4,%5,%6,%7}, {%8,%9}, {%0,%1,%2,%3};" \
        : "+f"((d)[0]), "+f"((d)[1]), "+f"((d)[2]), "+f"((d)[3]) \
        : "r"((a)[0]), "r"((a)[1]), "r"((a)[2]), "r"((a)[3]), "r"(b0), "r"(b1))

// ------------------------- prep kernels -----------------------------------
__global__ void concat_convert_k(const float* __restrict__ prior, const float* __restrict__ gen){
    int i = blockIdx.x * blockDim.x + threadIdx.x;
    if (i >= BB * CCH) return;
    int b = i / CCH, c = i % CCH;
    float v = (c < PPD) ? prior[(size_t)b * PPD + c] : gen[(size_t)b * GGD + (c - PPD)];
    __half hi, lo; split_f32(v, hi, lo);
    g_comb_h[i] = hi; g_comb_l[i] = lo;
}
__global__ void pers_convert_k(const float* __restrict__ pers){
    int i = blockIdx.x * blockDim.x + threadIdx.x;
    if (i >= BB * GGD) return;
    __half hi, lo; split_f32(pers[i], hi, lo);
    g_pers_h[i] = hi; g_pers_l[i] = lo;
}

// One fused kernel transposes+converts ALL six weights.
__global__ void transpose_all_k(const float* __restrict__ Wp0, const float* __restrict__ Wg0,
                                const float* __restrict__ Wt0, const float* __restrict__ Wp1,
                                const float* __restrict__ Wg1, const float* __restrict__ Wt1){
    __shared__ float tile[32][33];
    int t = blockIdx.z;
    int bid = blockIdx.x;
    const float* src; __half* dh; __half* dl; int Kd, Nd, idx;
    if      (bid < 384)  { src=Wp0; dh=g_wppn0_h; dl=g_wppn0_l; Kd=CCH; Nd=H0; idx=bid; }
    else if (bid < 640)  { src=Wg0; dh=g_wgt0_h;  dl=g_wgt0_l;  Kd=H0;  Nd=H0; idx=bid-384; }
    else if (bid < 896)  { src=Wt0; dh=g_wtw0_h;  dl=g_wtw0_l;  Kd=GGD; Nd=H0; idx=bid-640; }
    else if (bid < 1088) { src=Wp1; dh=g_wppn1_h; dl=g_wppn1_l; Kd=CCH; Nd=H1; idx=bid-896; }
    else if (bid < 1152) { src=Wg1; dh=g_wgt1_h;  dl=g_wgt1_l;  Kd=H1;  Nd=H1; idx=bid-1088; }
    else                 { src=Wt1; dh=g_wtw1_h;  dl=g_wtw1_l;  Kd=H0;  Nd=H1; idx=bid-1152; }
    int kt = Kd / 32;
    int k0 = (idx % kt) * 32, n0 = (idx / kt) * 32;
    src += (size_t)t * Kd * Nd;
    dh  += (size_t)t * Nd * Kd;
    dl  += (size_t)t * Nd * Kd;
    int x = threadIdx.x;
    for (int yy = threadIdx.y; yy < 32; yy += 8)
        tile[yy][x] = src[(size_t)(k0 + yy) * Nd + n0 + x];
    __syncthreads();
    for (int yy = threadIdx.y; yy < 32; yy += 8){
        float v = tile[x][yy];
        __half hi, lo; split_f32(v, hi, lo);
        size_t o = (size_t)(n0 + yy) * Kd + k0 + x;
        dh[o] = hi; dl[o] = lo;
    }
}

// ------------------------- fp16-split GEMM ---------------------------------
// CTA 128x128, 8 warps (4M x 2N), warp tile 32x64 (R13-proven config).
// KC=64, 2-stage, SW128, one __syncthreads per chunk.
// BPL=2: D = Ah*Bh + Ah*Bl ; BPL=1 (gates): D = Ah*Bh (sigmoid-damped error).
// wlo=0 skips the lo-plane output store (x0's lo plane has no consumer).
#define ROWB 128
#define TILEB 16384
#define STG   49152
#define SMEM_DYN (2*STG)

template<int BPL>
__global__ void __launch_bounds__(256, 2) gemm_fp16s(
    int a_id, size_t a_tstr, int lda, int K,
    int b_id, const float* __restrict__ bias,
    int aux_id, int out_id, int Ntot, int epi, int wlo)
{
    extern __shared__ char smem[];
    uint32_t sb = smem_u32(smem);
    int tid = threadIdx.x, wid = tid >> 5, lid = tid & 31;
    int warp_m = wid & 3, warp_n = wid >> 2;     // 4 M-blocks x 2 N-blocks
    int t  = blockIdx.z;
    int m0 = blockIdx.x * 128;
    int n0 = blockIdx.y * 128;

    const __half* Ah = get_hbuf(a_id, 0) + (size_t)t * a_tstr + (size_t)m0 * lda;
    const __half* Bh = get_hbuf(b_id, 0) + ((size_t)t * Ntot + n0) * K;
    const __half* Bl = get_hbuf(b_id, 1) + ((size_t)t * Ntot + n0) * K;

    float acc[2][8][4];
    #pragma unroll
    for (int mi = 0; mi < 2; mi++)
        #pragma unroll
        for (int ni = 0; ni < 8; ni++)
            #pragma unroll
            for (int j = 0; j < 4; j++) acc[mi][ni][j] = 0.f;

    int nk = K >> 6;

    // ---- lane-constant ldmatrix base offsets (s=0); s-step is XOR (s<<5) ----
    // Base bits [6:5] are zero (cb is 0/16), so +s*32 never carries; SW128 mask
    // depends only on row bits [9:7]. (Validated in R13: bitwise-equal result.)
    int lq = lid >> 3, lr = lid & 7;
    uint32_t a_row = (uint32_t)(warp_m * 32 + ((lq & 1) << 3) + lr);
    uint32_t a_cb  = (uint32_t)((lq >> 1) << 4);
    uint32_t b_row = (uint32_t)(warp_n * 64 + ((lq >> 1) << 3) + lr);
    uint32_t b_cb  = (uint32_t)((lq & 1) << 4);
    uint32_t aoff0[2], boff0[4];
    #pragma unroll
    for (int mi = 0; mi < 2; mi++)
        aoff0[mi] = sw128((a_row + mi * 16) * ROWB + a_cb);
    #pragma unroll
    for (int p = 0; p < 4; p++)
        boff0[p] = sw128((b_row + p * 16) * ROWB + b_cb);

    // ---- loader: tiles x 1024 16B-slots; 256 threads x 4 slots per tile ----
    int c8  = tid & 7;
    int r32 = tid >> 3;
    uint32_t dofs[4];
    #pragma unroll
    for (int i = 0; i < 4; i++)
        dofs[i] = sw128((uint32_t)((r32 + 32 * i) * ROWB + c8 * 16));

    auto load_chunk = [&](int kc, int stage_sel){
        uint32_t stg = (uint32_t)stage_sel * (uint32_t)STG;
        const __half* sA = Ah + kc * 64;
        const __half* sH = Bh + kc * 64;
        uint32_t baseA = sb + stg;
        uint32_t baseH = sb + stg + (uint32_t)TILEB;
        #pragma unroll
        for (int i = 0; i < 4; i++){
            int row = r32 + 32 * i;
            cp16(baseA + dofs[i], sA + (size_t)row * lda + c8 * 8);
            cp16(baseH + dofs[i], sH + (size_t)row * K   + c8 * 8);
        }
        if (BPL == 2){
            const __half* sL = Bl + kc * 64;
            uint32_t baseL = sb + stg + 2u * (uint32_t)TILEB;
            #pragma unroll
            for (int i = 0; i < 4; i++){
                int row = r32 + 32 * i;
                cp16(baseL + dofs[i], sL + (size_t)row * K + c8 * 8);
            }
        }
        CP_COMMIT();
    };

    load_chunk(0, 0);

    for (int kc = 0; kc < nk; kc++){
        asm volatile("cp.async.wait_group 0;" ::: "memory");
        __syncthreads();   // loads of kc visible; all warps done reading other stage
        if (kc + 1 < nk)
            load_chunk(kc + 1, (kc + 1) & 1);   // overlaps compute of kc

        uint32_t stg_b = sb + (uint32_t)(kc & 1) * STG;
        uint32_t sAh = stg_b;
        uint32_t sBh = stg_b + TILEB;
        uint32_t sBl = stg_b + 2 * TILEB;

        #pragma unroll
        for (int s = 0; s < 4; s++){
            uint32_t sx = (uint32_t)(s << 5);
            uint32_t ah[2][4];
            #pragma unroll
            for (int mi = 0; mi < 2; mi++)
                LDSM_X4(ah[mi][0], ah[mi][1], ah[mi][2], ah[mi][3], sAh + (aoff0[mi] ^ sx));
            #pragma unroll
            for (int p = 0; p < 4; p++){
                uint32_t bh0, bh1, bh2, bh3;
                uint32_t bl0, bl1, bl2, bl3;
                LDSM_X4(bh0, bh1, bh2, bh3, sBh + (boff0[p] ^ sx));
                if (BPL == 2){
                    LDSM_X4(bl0, bl1, bl2, bl3, sBl + (boff0[p] ^ sx));
                }
                #pragma unroll
                for (int mi = 0; mi < 2; mi++){
                    MMA16816(acc[mi][2*p],   ah[mi], bh0, bh1);
                    MMA16816(acc[mi][2*p+1], ah[mi], bh2, bh3);
                    if (BPL == 2){
                        MMA16816(acc[mi][2*p],   ah[mi], bl0, bl1);
                        MMA16816(acc[mi][2*p+1], ah[mi], bl2, bl3);
                    }
                }
            }
        }
    }

    // ---------------- epilogue ----------------
    const float* biasp = bias + (size_t)t * Ntot;
    const __half* axh = nullptr; const __half* axl = nullptr;
    if (epi){
        axh = get_hbuf(aux_id, 0) + (size_t)t * BB * Ntot;
        axl = get_hbuf(aux_id, 1) + (size_t)t * BB * Ntot;
    }
    __half* oh = get_hbuf(out_id, 0) + (size_t)t * BB * Ntot;
    __half* ol = get_hbuf(out_id, 1) + (size_t)t * BB * Ntot;

    int g = lid >> 2, tig = lid & 3;
    #pragma unroll
    for (int mi = 0; mi < 2; mi++){
        #pragma unroll
        for (int ni = 0; ni < 8; ni++){
            int col = n0 + warp_n * 64 + ni * 8 + 2 * tig;
            float2 bv = *(const float2*)(biasp + col);
            int row0 = m0 + warp_m * 32 + mi * 16 + g;
            #pragma unroll
            for (int h = 0; h < 2; h++){
                int row = row0 + h * 8;
                size_t off = (size_t)row * Ntot + col;
                float v0 = acc[mi][ni][2*h]   + bv.x;
                float v1 = acc[mi][ni][2*h+1] + bv.y;
                float a0 = 0.f, a1 = 0.f;
                if (epi){
                    __half2 hv = *(const __half2*)(axh + off);
                    __half2 lv = *(const __half2*)(axl + off);
                    a0 = __half2float(hv.x) + __half2float(lv.x);
                    a1 = __half2float(hv.y) + __half2float(lv.y);
                }
                float r0, r1;
                if (epi == 0){
                    r0 = fmaxf(v0, 0.f); r1 = fmaxf(v1, 0.f);
                } else if (epi == 1){
                    r0 = a0 * (1.f / (1.f + __expf(-2.f * v0)));
                    r1 = a1 * (1.f / (1.f + __expf(-2.f * v1)));
                } else {
                    r0 = fmaxf(v0 * a0, 0.f); r1 = fmaxf(v1 * a1, 0.f);
                }
                __half h0v, l0v, h1v, l1v;
                split_f32(r0, h0v, l0v); split_f32(r1, h1v, l1v);
                *(__half2*)(oh + off) = __halves2half2(h0v, h1v);
                if (wlo)
                    *(__half2*)(ol + off) = __halves2half2(l0v, l1v);
            }
        }
    }
}

// ------------------------- output layer -----------------------------------
__global__ void out_k(const float* __restrict__ W2, const float* __restrict__ b2,
                      float* __restrict__ out){
    int b = blockIdx.x;
    int wid = threadIdx.x >> 5, lid = threadIdx.x & 31;   // wid = task
    const __half* xh = get_hbuf(HP_X1, 0) + ((size_t)wid * BB + b) * H1;
    const __half* xl = get_hbuf(HP_X1, 1) + ((size_t)wid * BB + b) * H1;
    const float* wr = W2 + (size_t)wid * H1;
    float s = 0.f;
    #pragma unroll
    for (int j = 0; j < 8; j++){
        int i = lid + 32 * j;
        s += (__half2float(xh[i]) + __half2float(xl[i])) * wr[i];
    }
    #pragma unroll
    for (int o = 16; o > 0; o >>= 1)
        s += __shfl_down_sync(0xFFFFFFFFu, s, o);
    if (lid == 0) out[(size_t)b * TT + wid] = s + b2[wid];
}

// ------------------------- launch -----------------------------------------
extern "C" void kernel_launch(void* const* d_in, const int* in_sizes, int n_in,
                              void* d_out, int out_size) {
    const float* prior    = (const float*)d_in[0];
    const float* gen      = (const float*)d_in[1];
    const float* pers     = (const float*)d_in[2];
    const float* tower_W0 = (const float*)d_in[3];
    const float* tower_b0 = (const float*)d_in[4];
    const float* tower_W1 = (const float*)d_in[5];
    const float* tower_b1 = (const float*)d_in[6];
    const float* tower_W2 = (const float*)d_in[7];
    const float* tower_b2 = (const float*)d_in[8];
    const float* ppn0_W   = (const float*)d_in[9];
    const float* ppn0_b   = (const float*)d_in[10];
    const float* gate0_W  = (const float*)d_in[11];
    const float* gate0_b  = (const float*)d_in[12];
    const float* ppn1_W   = (const float*)d_in[13];
    const float* ppn1_b   = (const float*)d_in[14];
    const float* gate1_W  = (const float*)d_in[15];
    const float* gate1_b  = (const float*)d_in[16];

    cudaFuncSetAttribute(gemm_fp16s<2>,
                         cudaFuncAttributeMaxDynamicSharedMemorySize, SMEM_DYN);
    cudaFuncSetAttribute(gemm_fp16s<1>,
                         cudaFuncAttributeMaxDynamicSharedMemorySize, SMEM_DYN);

    // launches 0,1,2: prep — launch index 5 (ncu -s 5 -c 1) is tower0 GEMM
    concat_convert_k<<<(BB * CCH) / 256, 256>>>(prior, gen);
    pers_convert_k<<<(BB * GGD) / 256, 256>>>(pers);
    transpose_all_k<<<dim3(1280, 1, TT), dim3(32, 8)>>>(
        ppn0_W, gate0_W, tower_W0, ppn1_W, gate1_W, tower_W1);

    // ppn0: h0 = relu(comb @ W + b)                 [K=768, N=512]   2-plane
    gemm_fp16s<2><<<dim3(BB/128, H0/128, TT), 256, SMEM_DYN>>>(
        HP_COMB, 0, CCH, CCH, HP_WPPN0, ppn0_b, 0, HP_H0, H0, 0, 1);
    // gate0: g0 = h0 * sigmoid(2*(h0 @ Wg + b))     [K=512, N=512]   1-plane (damped)
    gemm_fp16s<1><<<dim3(BB/128, H0/128, TT), 256, SMEM_DYN>>>(
        HP_H0, (size_t)BB*H0, H0, H0, HP_WGT0, gate0_b, HP_H0, HP_G0, H0, 1, 1);
    // tower0: x0 = relu((pers @ W0 + b0) * g0)      [K=512, N=512]   2-plane (profiled)
    gemm_fp16s<2><<<dim3(BB/128, H0/128, TT), 256, SMEM_DYN>>>(
        HP_PERS, 0, GGD, GGD, HP_WTW0, tower_b0, HP_G0, HP_X0, H0, 2, 0);
    // ppn1: h1 = relu(comb @ W + b)                 [K=768, N=256]   2-plane
    gemm_fp16s<2><<<dim3(BB/128, H1/128, TT), 256, SMEM_DYN>>>(
        HP_COMB, 0, CCH, CCH, HP_WPPN1, ppn1_b, 0, HP_H1, H1, 0, 1);
    // gate1: g1 = h1 * sigmoid(2*(h1 @ Wg + b))     [K=256, N=256]   1-plane (damped)
    gemm_fp16s<1><<<dim3(BB/128, H1/128, TT), 256, SMEM_DYN>>>(
        HP_H1, (size_t)BB*H1, H1, H1, HP_WGT1, gate1_b, HP_H1, HP_G1, H1, 1, 1);
    // tower1: x1 = relu((x0 @ W1 + b1) * g1)        [K=512, N=256]   2-plane
    gemm_fp16s<2><<<dim3(BB/128, H1/128, TT), 256, SMEM_DYN>>>(
        HP_X0, (size_t)BB*H0, H0, H0, HP_WTW1, tower_b1, HP_G1, HP_X1, H1, 2, 1);

    out_k<<<BB, 256>>>(tower_W2, tower_b2, (float*)d_out);
}

// round 17
// speedup vs baseline: 1.2144x; 1.1663x over previous
#include <cuda_runtime.h>
#include <cuda_fp16.h>
#include <cstdint>
#include <cstddef>

#define BB  8192
#define TT  8
#define PPD 256
#define GGD 512
#define CCH 768
#define H0  512
#define H1  256

// ------------------------- device scratch (352 MB total) -------------------
__device__ __align__(256) __half g_comb_h [(size_t)BB*CCH];
__device__ __align__(256) __half g_comb_l [(size_t)BB*CCH];
__device__ __align__(256) __half g_pers_h [(size_t)BB*GGD];
__device__ __align__(256) __half g_pers_l [(size_t)BB*GGD];
__device__ __align__(256) __half g_wppn0_h[(size_t)TT*H0*CCH];
__device__ __align__(256) __half g_wppn0_l[(size_t)TT*H0*CCH];
__device__ __align__(256) __half g_wgt0_h [(size_t)TT*H0*H0];
__device__ __align__(256) __half g_wgt0_l [(size_t)TT*H0*H0];
__device__ __align__(256) __half g_wtw0_h [(size_t)TT*H0*GGD];
__device__ __align__(256) __half g_wtw0_l [(size_t)TT*H0*GGD];
__device__ __align__(256) __half g_wppn1_h[(size_t)TT*H1*CCH];
__device__ __align__(256) __half g_wppn1_l[(size_t)TT*H1*CCH];
__device__ __align__(256) __half g_wgt1_h [(size_t)TT*H1*H1];
__device__ __align__(256) __half g_wgt1_l [(size_t)TT*H1*H1];
__device__ __align__(256) __half g_wtw1_h [(size_t)TT*H1*H0];
__device__ __align__(256) __half g_wtw1_l [(size_t)TT*H1*H0];

// Aliased activation pools (stream order makes every overwrite safe; see R5/R6)
#define P64  67108864ull
#define P32  33554432ull
__device__ __align__(256) unsigned char g_poolA[2ull*P64];
__device__ __align__(256) unsigned char g_poolB[2ull*P64];

enum { HP_COMB=0, HP_PERS, HP_WPPN0, HP_WGT0, HP_WTW0, HP_WPPN1, HP_WGT1, HP_WTW1,
       HP_H0, HP_X0, HP_G0, HP_H1, HP_G1, HP_X1 };

__device__ __forceinline__ __half* get_hbuf(int id, int plane){
    switch(id){
        case HP_COMB:  return plane ? g_comb_l  : g_comb_h;
        case HP_PERS:  return plane ? g_pers_l  : g_pers_h;
        case HP_WPPN0: return plane ? g_wppn0_l : g_wppn0_h;
        case HP_WGT0:  return plane ? g_wgt0_l  : g_wgt0_h;
        case HP_WTW0:  return plane ? g_wtw0_l  : g_wtw0_h;
        case HP_WPPN1: return plane ? g_wppn1_l : g_wppn1_h;
        case HP_WGT1:  return plane ? g_wgt1_l  : g_wgt1_h;
        case HP_WTW1:  return plane ? g_wtw1_l  : g_wtw1_h;
        case HP_H0:    return (__half*)(g_poolA + (plane ? P64 : 0));
        case HP_X0:    return (__half*)(g_poolA + (plane ? P64 : 0));
        case HP_G0:    return (__half*)(g_poolB + (plane ? P64 : 0));
        case HP_H1:    return (__half*)(g_poolB + (plane ? P32 : 0));
        case HP_G1:    return (__half*)(g_poolB + P64 + (plane ? P32 : 0));
        default:       return (__half*)(g_poolB + (plane ? P32 : 0));   // HP_X1
    }
}

// ------------------------- small helpers ----------------------------------
__device__ __forceinline__ uint32_t smem_u32(const void* p){
    uint32_t a;
    asm("{ .reg .u64 t; cvta.to.shared.u64 t, %1; cvt.u32.u64 %0, t; }" : "=r"(a) : "l"(p));
    return a;
}
__device__ __forceinline__ void split_f32(float v, __half& hi, __half& lo){
    hi = __float2half_rn(v);
    lo = __float2half_rn(v - __half2float(hi));
}
__device__ __forceinline__ void cp16(uint32_t dst, const void* src){
    asm volatile("cp.async.cg.shared.global [%0], [%1], 16;" :: "r"(dst), "l"(src));
}
#define CP_COMMIT() asm volatile("cp.async.commit_group;" ::: "memory")
// SW128 swizzle: bits [6:4] ^= bits [9:7] — conflict-free ldmatrix at 128B rows
__device__ __forceinline__ uint32_t sw128(uint32_t off){ return off ^ ((off >> 3) & 0x70); }
#define LDSM_X4(r0,r1,r2,r3,addr) \
    asm volatile("ldmatrix.sync.aligned.m8n8.x4.shared.b16 {%0,%1,%2,%3}, [%4];" \
        : "=r"(r0), "=r"(r1), "=r"(r2), "=r"(r3) : "r"(addr))
#define MMA16816(d, a, b0, b1) \
    asm volatile("mma.sync.aligned.m16n8k16.row.col.f32.f16.f16.f32 " \
        "{%0,%1,%2,%3}, {%4,%5,%6,%7}, {%8,%9}, {%0,%1,%2,%3};" \
        : "+f"((d)[0]), "+f"((d)[1]), "+f"((d)[2]), "+f"((d)[3]) \
        : "r"((a)[0]), "r"((a)[1]), "r"((a)[2]), "r"((a)[3]), "r"(b0), "r"(b1))

// ------------------------- prep kernels -----------------------------------
// comb/pers lo planes are dead (A lo-plane unused in all GEMMs) — hi only.
__global__ void concat_convert_k(const float* __restrict__ prior, const float* __restrict__ gen){
    int i = blockIdx.x * blockDim.x + threadIdx.x;
    if (i >= BB * CCH) return;
    int b = i / CCH, c = i % CCH;
    float v = (c < PPD) ? prior[(size_t)b * PPD + c] : gen[(size_t)b * GGD + (c - PPD)];
    g_comb_h[i] = __float2half_rn(v);
}
__global__ void pers_convert_k(const float* __restrict__ pers){
    int i = blockIdx.x * blockDim.x + threadIdx.x;
    if (i >= BB * GGD) return;
    g_pers_h[i] = __float2half_rn(pers[i]);
}

// One fused kernel transposes+converts ALL six weights.
__global__ void transpose_all_k(const float* __restrict__ Wp0, const float* __restrict__ Wg0,
                                const float* __restrict__ Wt0, const float* __restrict__ Wp1,
                                const float* __restrict__ Wg1, const float* __restrict__ Wt1){
    __shared__ float tile[32][33];
    int t = blockIdx.z;
    int bid = blockIdx.x;
    const float* src; __half* dh; __half* dl; int Kd, Nd, idx;
    if      (bid < 384)  { src=Wp0; dh=g_wppn0_h; dl=g_wppn0_l; Kd=CCH; Nd=H0; idx=bid; }
    else if (bid < 640)  { src=Wg0; dh=g_wgt0_h;  dl=g_wgt0_l;  Kd=H0;  Nd=H0; idx=bid-384; }
    else if (bid < 896)  { src=Wt0; dh=g_wtw0_h;  dl=g_wtw0_l;  Kd=GGD; Nd=H0; idx=bid-640; }
    else if (bid < 1088) { src=Wp1; dh=g_wppn1_h; dl=g_wppn1_l; Kd=CCH; Nd=H1; idx=bid-896; }
    else if (bid < 1152) { src=Wg1; dh=g_wgt1_h;  dl=g_wgt1_l;  Kd=H1;  Nd=H1; idx=bid-1088; }
    else                 { src=Wt1; dh=g_wtw1_h;  dl=g_wtw1_l;  Kd=H0;  Nd=H1; idx=bid-1152; }
    int kt = Kd / 32;
    int k0 = (idx % kt) * 32, n0 = (idx / kt) * 32;
    src += (size_t)t * Kd * Nd;
    dh  += (size_t)t * Nd * Kd;
    dl  += (size_t)t * Nd * Kd;
    int x = threadIdx.x;
    for (int yy = threadIdx.y; yy < 32; yy += 8)
        tile[yy][x] = src[(size_t)(k0 + yy) * Nd + n0 + x];
    __syncthreads();
    for (int yy = threadIdx.y; yy < 32; yy += 8){
        float v = tile[x][yy];
        __half hi, lo; split_f32(v, hi, lo);
        size_t o = (size_t)(n0 + yy) * Kd + k0 + x;
        dh[o] = hi; dl[o] = lo;
    }
}

// ------------------------- fp16-split GEMM ---------------------------------
// CTA 128x128, 8 warps (4M x 2N), warp tile 32x64 (R13-proven config).
// KC=64, 2-stage, SW128, one __syncthreads per chunk.
// BPL=2: D = Ah*Bh + Ah*Bl ; BPL=1: D = Ah*Bh (error quadrature-budgeted).
// wlo=0 skips the lo-plane output store (x0's lo plane has no consumer).
#define ROWB 128
#define TILEB 16384
#define STG   49152
#define SMEM_DYN (2*STG)

template<int BPL>
__global__ void __launch_bounds__(256, 2) gemm_fp16s(
    int a_id, size_t a_tstr, int lda, int K,
    int b_id, const float* __restrict__ bias,
    int aux_id, int out_id, int Ntot, int epi, int wlo)
{
    extern __shared__ char smem[];
    uint32_t sb = smem_u32(smem);
    int tid = threadIdx.x, wid = tid >> 5, lid = tid & 31;
    int warp_m = wid & 3, warp_n = wid >> 2;     // 4 M-blocks x 2 N-blocks
    int t  = blockIdx.z;
    int m0 = blockIdx.x * 128;
    int n0 = blockIdx.y * 128;

    const __half* Ah = get_hbuf(a_id, 0) + (size_t)t * a_tstr + (size_t)m0 * lda;
    const __half* Bh = get_hbuf(b_id, 0) + ((size_t)t * Ntot + n0) * K;
    const __half* Bl = get_hbuf(b_id, 1) + ((size_t)t * Ntot + n0) * K;

    float acc[2][8][4];
    #pragma unroll
    for (int mi = 0; mi < 2; mi++)
        #pragma unroll
        for (int ni = 0; ni < 8; ni++)
            #pragma unroll
            for (int j = 0; j < 4; j++) acc[mi][ni][j] = 0.f;

    int nk = K >> 6;

    // ---- lane-constant ldmatrix base offsets (s=0); s-step is XOR (s<<5) ----
    int lq = lid >> 3, lr = lid & 7;
    uint32_t a_row = (uint32_t)(warp_m * 32 + ((lq & 1) << 3) + lr);
    uint32_t a_cb  = (uint32_t)((lq >> 1) << 4);
    uint32_t b_row = (uint32_t)(warp_n * 64 + ((lq >> 1) << 3) + lr);
    uint32_t b_cb  = (uint32_t)((lq & 1) << 4);
    uint32_t aoff0[2], boff0[4];
    #pragma unroll
    for (int mi = 0; mi < 2; mi++)
        aoff0[mi] = sw128((a_row + mi * 16) * ROWB + a_cb);
    #pragma unroll
    for (int p = 0; p < 4; p++)
        boff0[p] = sw128((b_row + p * 16) * ROWB + b_cb);

    // ---- loader: tiles x 1024 16B-slots; 256 threads x 4 slots per tile ----
    int c8  = tid & 7;
    int r32 = tid >> 3;
    uint32_t dofs[4];
    #pragma unroll
    for (int i = 0; i < 4; i++)
        dofs[i] = sw128((uint32_t)((r32 + 32 * i) * ROWB + c8 * 16));

    auto load_chunk = [&](int kc, int stage_sel){
        uint32_t stg = (uint32_t)stage_sel * (uint32_t)STG;
        const __half* sA = Ah + kc * 64;
        const __half* sH = Bh + kc * 64;
        uint32_t baseA = sb + stg;
        uint32_t baseH = sb + stg + (uint32_t)TILEB;
        #pragma unroll
        for (int i = 0; i < 4; i++){
            int row = r32 + 32 * i;
            cp16(baseA + dofs[i], sA + (size_t)row * lda + c8 * 8);
            cp16(baseH + dofs[i], sH + (size_t)row * K   + c8 * 8);
        }
        if (BPL == 2){
            const __half* sL = Bl + kc * 64;
            uint32_t baseL = sb + stg + 2u * (uint32_t)TILEB;
            #pragma unroll
            for (int i = 0; i < 4; i++){
                int row = r32 + 32 * i;
                cp16(baseL + dofs[i], sL + (size_t)row * K + c8 * 8);
            }
        }
        CP_COMMIT();
    };

    load_chunk(0, 0);

    for (int kc = 0; kc < nk; kc++){
        asm volatile("cp.async.wait_group 0;" ::: "memory");
        __syncthreads();   // loads of kc visible; all warps done reading other stage
        if (kc + 1 < nk)
            load_chunk(kc + 1, (kc + 1) & 1);   // overlaps compute of kc

        uint32_t stg_b = sb + (uint32_t)(kc & 1) * STG;
        uint32_t sAh = stg_b;
        uint32_t sBh = stg_b + TILEB;
        uint32_t sBl = stg_b + 2 * TILEB;

        #pragma unroll
        for (int s = 0; s < 4; s++){
            uint32_t sx = (uint32_t)(s << 5);
            uint32_t ah[2][4];
            #pragma unroll
            for (int mi = 0; mi < 2; mi++)
                LDSM_X4(ah[mi][0], ah[mi][1], ah[mi][2], ah[mi][3], sAh + (aoff0[mi] ^ sx));
            #pragma unroll
            for (int p = 0; p < 4; p++){
                uint32_t bh0, bh1, bh2, bh3;
                uint32_t bl0, bl1, bl2, bl3;
                LDSM_X4(bh0, bh1, bh2, bh3, sBh + (boff0[p] ^ sx));
                if (BPL == 2){
                    LDSM_X4(bl0, bl1, bl2, bl3, sBl + (boff0[p] ^ sx));
                }
                #pragma unroll
                for (int mi = 0; mi < 2; mi++){
                    MMA16816(acc[mi][2*p],   ah[mi], bh0, bh1);
                    MMA16816(acc[mi][2*p+1], ah[mi], bh2, bh3);
                    if (BPL == 2){
                        MMA16816(acc[mi][2*p],   ah[mi], bl0, bl1);
                        MMA16816(acc[mi][2*p+1], ah[mi], bl2, bl3);
                    }
                }
            }
        }
    }

    // ---------------- epilogue ----------------
    const float* biasp = bias + (size_t)t * Ntot;
    const __half* axh = nullptr; const __half* axl = nullptr;
    if (epi){
        axh = get_hbuf(aux_id, 0) + (size_t)t * BB * Ntot;
        axl = get_hbuf(aux_id, 1) + (size_t)t * BB * Ntot;
    }
    __half* oh = get_hbuf(out_id, 0) + (size_t)t * BB * Ntot;
    __half* ol = get_hbuf(out_id, 1) + (size_t)t * BB * Ntot;

    int g = lid >> 2, tig = lid & 3;
    #pragma unroll
    for (int mi = 0; mi < 2; mi++){
        #pragma unroll
        for (int ni = 0; ni < 8; ni++){
            int col = n0 + warp_n * 64 + ni * 8 + 2 * tig;
            float2 bv = *(const float2*)(biasp + col);
            int row0 = m0 + warp_m * 32 + mi * 16 + g;
            #pragma unroll
            for (int h = 0; h < 2; h++){
                int row = row0 + h * 8;
                size_t off = (size_t)row * Ntot + col;
                float v0 = acc[mi][ni][2*h]   + bv.x;
                float v1 = acc[mi][ni][2*h+1] + bv.y;
                float a0 = 0.f, a1 = 0.f;
                if (epi){
                    __half2 hv = *(const __half2*)(axh + off);
                    __half2 lv = *(const __half2*)(axl + off);
                    a0 = __half2float(hv.x) + __half2float(lv.x);
                    a1 = __half2float(hv.y) + __half2float(lv.y);
                }
                float r0, r1;
                if (epi == 0){
                    r0 = fmaxf(v0, 0.f); r1 = fmaxf(v1, 0.f);
                } else if (epi == 1){
                    r0 = a0 * (1.f / (1.f + __expf(-2.f * v0)));
                    r1 = a1 * (1.f / (1.f + __expf(-2.f * v1)));
                } else {
                    r0 = fmaxf(v0 * a0, 0.f); r1 = fmaxf(v1 * a1, 0.f);
                }
                __half h0v, l0v, h1v, l1v;
                split_f32(r0, h0v, l0v); split_f32(r1, h1v, l1v);
                *(__half2*)(oh + off) = __halves2half2(h0v, h1v);
                if (wlo)
                    *(__half2*)(ol + off) = __halves2half2(l0v, l1v);
            }
        }
    }
}

// ------------------------- output layer -----------------------------------
__global__ void out_k(const float* __restrict__ W2, const float* __restrict__ b2,
                      float* __restrict__ out){
    int b = blockIdx.x;
    int wid = threadIdx.x >> 5, lid = threadIdx.x & 31;   // wid = task
    const __half* xh = get_hbuf(HP_X1, 0) + ((size_t)wid * BB + b) * H1;
    const __half* xl = get_hbuf(HP_X1, 1) + ((size_t)wid * BB + b) * H1;
    const float* wr = W2 + (size_t)wid * H1;
    float s = 0.f;
    #pragma unroll
    for (int j = 0; j < 8; j++){
        int i = lid + 32 * j;
        s += (__half2float(xh[i]) + __half2float(xl[i])) * wr[i];
    }
    #pragma unroll
    for (int o = 16; o > 0; o >>= 1)
        s += __shfl_down_sync(0xFFFFFFFFu, s, o);
    if (lid == 0) out[(size_t)b * TT + wid] = s + b2[wid];
}

// ------------------------- launch -----------------------------------------
extern "C" void kernel_launch(void* const* d_in, const int* in_sizes, int n_in,
                              void* d_out, int out_size) {
    const float* prior    = (const float*)d_in[0];
    const float* gen      = (const float*)d_in[1];
    const float* pers     = (const float*)d_in[2];
    const float* tower_W0 = (const float*)d_in[3];
    const float* tower_b0 = (const float*)d_in[4];
    const float* tower_W1 = (const float*)d_in[5];
    const float* tower_b1 = (const float*)d_in[6];
    const float* tower_W2 = (const float*)d_in[7];
    const float* tower_b2 = (const float*)d_in[8];
    const float* ppn0_W   = (const float*)d_in[9];
    const float* ppn0_b   = (const float*)d_in[10];
    const float* gate0_W  = (const float*)d_in[11];
    const float* gate0_b  = (const float*)d_in[12];
    const float* ppn1_W   = (const float*)d_in[13];
    const float* ppn1_b   = (const float*)d_in[14];
    const float* gate1_W  = (const float*)d_in[15];
    const float* gate1_b  = (const float*)d_in[16];

    cudaFuncSetAttribute(gemm_fp16s<2>,
                         cudaFuncAttributeMaxDynamicSharedMemorySize, SMEM_DYN);
    cudaFuncSetAttribute(gemm_fp16s<1>,
                         cudaFuncAttributeMaxDynamicSharedMemorySize, SMEM_DYN);

    // launches 0,1,2: prep — launch index 5 (ncu -s 5 -c 1) is tower0 GEMM
    concat_convert_k<<<(BB * CCH) / 256, 256>>>(prior, gen);
    pers_convert_k<<<(BB * GGD) / 256, 256>>>(pers);
    transpose_all_k<<<dim3(1280, 1, TT), dim3(32, 8)>>>(
        ppn0_W, gate0_W, tower_W0, ppn1_W, gate1_W, tower_W1);

    // ppn0: h0 = relu(comb @ W + b)                 [K=768, N=512]   1-plane
    gemm_fp16s<1><<<dim3(BB/128, H0/128, TT), 256, SMEM_DYN>>>(
        HP_COMB, 0, CCH, CCH, HP_WPPN0, ppn0_b, 0, HP_H0, H0, 0, 1);
    // gate0: g0 = h0 * sigmoid(2*(h0 @ Wg + b))     [K=512, N=512]   1-plane (damped)
    gemm_fp16s<1><<<dim3(BB/128, H0/128, TT), 256, SMEM_DYN>>>(
        HP_H0, (size_t)BB*H0, H0, H0, HP_WGT0, gate0_b, HP_H0, HP_G0, H0, 1, 1);
    // tower0: x0 = relu((pers @ W0 + b0) * g0)      [K=512, N=512]   2-plane (profiled control)
    gemm_fp16s<2><<<dim3(BB/128, H0/128, TT), 256, SMEM_DYN>>>(
        HP_PERS, 0, GGD, GGD, HP_WTW0, tower_b0, HP_G0, HP_X0, H0, 2, 0);
    // ppn1: h1 = relu(comb @ W + b)                 [K=768, N=256]   1-plane
    gemm_fp16s<1><<<dim3(BB/128, H1/128, TT), 256, SMEM_DYN>>>(
        HP_COMB, 0, CCH, CCH, HP_WPPN1, ppn1_b, 0, HP_H1, H1, 0, 1);
    // gate1: g1 = h1 * sigmoid(2*(h1 @ Wg + b))     [K=256, N=256]   1-plane (damped)
    gemm_fp16s<1><<<dim3(BB/128, H1/128, TT), 256, SMEM_DYN>>>(
        HP_H1, (size_t)BB*H1, H1, H1, HP_WGT1, gate1_b, HP_H1, HP_G1, H1, 1, 1);
    // tower1: x1 = relu((x0 @ W1 + b1) * g1)        [K=512, N=256]   2-plane
    gemm_fp16s<2><<<dim3(BB/128, H1/128, TT), 256, SMEM_DYN>>>(
        HP_X0, (size_t)BB*H0, H0, H0, HP_WTW1, tower_b1, HP_G1, HP_X1, H1, 2, 1);

    out_k<<<BB, 256>>>(tower_W2, tower_b2, (float*)d_out);
}